// round 1
// baseline (speedup 1.0000x reference)
#include <cuda_runtime.h>
#include <math.h>

#define Bsz 8192
#define Dd  1024
#define Kk  1024
#define CAP 10

// Scratch (device globals: allocation-free rule)
__device__ float g_Ux[(size_t)Bsz * 3 * Dd];   // x @ U            [B, 3D]
__device__ float g_Sr[(size_t)Bsz * Dd];       // state @ W_r      [B, D]
__device__ float g_Sg[(size_t)Bsz * Dd];       // state @ W_g      [B, D]
__device__ float g_v1[CAP * Dd];               // butterfly cos coeffs (permuted)
__device__ float g_v2[CAP * Dd];               // butterfly sin coeffs (permuted)

// ---------------------------------------------------------------------------
// Precompute v1/v2:  v1[i][m] = cos_list[i][ind_param[i][m]], etc.
// ind_param[i][m]: j = m >> (10-i), q = m & ((1<<(10-i))-1), src = (q<<i)+j
// cos_list = [cos(theta), cos(theta)], sin_list = [sin(theta), -sin(theta)]
// ---------------------------------------------------------------------------
__global__ void precompute_v(const float* __restrict__ theta) {
    int i = blockIdx.x;          // stage 0..9
    int m = threadIdx.x;         // 0..1023
    int bl = 10 - i;
    int j = m >> bl;
    int q = m & ((1 << bl) - 1);
    int src = (q << i) + j;
    float th = theta[i * 512 + (src & 511)];
    float c, s;
    __sincosf(th, &s, &c);
    // __sincosf is fast-math; use precise versions for safety:
    c = cosf(th);
    s = sinf(th);
    if (src >= 512) s = -s;
    g_v1[i * Dd + m] = c;
    g_v2[i * Dd + m] = s;
}

// ---------------------------------------------------------------------------
// Classic fp32 SGEMM: C[M,N] = A[M,K] @ B[K,N], all row-major.
// Tile 128x128x8, 256 threads, 8x8 per-thread microtile.
// M = gridDim.y*128, all dims divisible by tile sizes (8192/1024/3072, K=1024).
// ---------------------------------------------------------------------------
__global__ void __launch_bounds__(256) sgemm128(const float* __restrict__ A,
                                                const float* __restrict__ Bm,
                                                float* __restrict__ C,
                                                int N, int K) {
    __shared__ float As[8][128];
    __shared__ float Bs[8][128];
    const int tid = threadIdx.x;
    const int tx  = tid & 15;    // N dir (0..15)
    const int ty  = tid >> 4;    // M dir (0..15)
    const int rowA = blockIdx.y * 128;
    const int colB = blockIdx.x * 128;

    // global->shared load mapping
    const int a_r = tid >> 1;          // 0..127
    const int a_c = (tid & 1) * 4;     // 0 or 4
    const int b_r = tid >> 5;          // 0..7
    const int b_c = (tid & 31) * 4;    // 0..124

    const float* Aptr = A + (size_t)(rowA + a_r) * K + a_c;
    const float* Bptr = Bm + (size_t)b_r * N + colB + b_c;

    float acc[8][8];
#pragma unroll
    for (int i = 0; i < 8; i++)
#pragma unroll
        for (int j = 0; j < 8; j++) acc[i][j] = 0.f;

    for (int k0 = 0; k0 < K; k0 += 8) {
        float4 av = *(const float4*)(Aptr + k0);
        float4 bv = *(const float4*)(Bptr + (size_t)k0 * N);
        As[a_c + 0][a_r] = av.x;
        As[a_c + 1][a_r] = av.y;
        As[a_c + 2][a_r] = av.z;
        As[a_c + 3][a_r] = av.w;
        *(float4*)&Bs[b_r][b_c] = bv;
        __syncthreads();

#pragma unroll
        for (int kk = 0; kk < 8; kk++) {
            float4 a0 = *(const float4*)&As[kk][ty * 8];
            float4 a1 = *(const float4*)&As[kk][ty * 8 + 4];
            float4 b0 = *(const float4*)&Bs[kk][tx * 8];
            float4 b1 = *(const float4*)&Bs[kk][tx * 8 + 4];
            float ra[8] = {a0.x, a0.y, a0.z, a0.w, a1.x, a1.y, a1.z, a1.w};
            float rb[8] = {b0.x, b0.y, b0.z, b0.w, b1.x, b1.y, b1.z, b1.w};
#pragma unroll
            for (int i = 0; i < 8; i++)
#pragma unroll
                for (int j = 0; j < 8; j++)
                    acc[i][j] = fmaf(ra[i], rb[j], acc[i][j]);
        }
        __syncthreads();
    }

#pragma unroll
    for (int i = 0; i < 8; i++) {
        size_t row = (size_t)(rowA + ty * 8 + i);
        float* cp = C + row * N + colB + tx * 8;
        float4 o0 = {acc[i][0], acc[i][1], acc[i][2], acc[i][3]};
        float4 o1 = {acc[i][4], acc[i][5], acc[i][6], acc[i][7]};
        *(float4*)(cp)     = o0;
        *(float4*)(cp + 4) = o1;
    }
}

// ---------------------------------------------------------------------------
// Fused gates + butterfly + modReLU + blend. One block per batch row.
// h_new[j] = h[j]*v1[i][j] + h[j^mask]*v2[i][j^mask],  mask = 512>>i
// ---------------------------------------------------------------------------
__global__ void __launch_bounds__(256) fuse_kernel(const float* __restrict__ state,
                                                   const float* __restrict__ bias_r,
                                                   const float* __restrict__ bias_g,
                                                   const float* __restrict__ bias_c,
                                                   float* __restrict__ out) {
    __shared__ float hbuf[2][Dd];
    const int b = blockIdx.x;
    const int t = threadIdx.x;
    const float* srow  = state + (size_t)b * Dd;
    const float* uxrow = g_Ux  + (size_t)b * (3 * Dd);
    const float* srp   = g_Sr  + (size_t)b * Dd;
    const float* sgp   = g_Sg  + (size_t)b * Dd;

    float st[4], rr[4], gg[4];
#pragma unroll
    for (int i = 0; i < 4; i++) {
        int j = t + i * 256;
        float s = srow[j];
        st[i] = s;
        hbuf[0][j] = s;
        float pr = uxrow[Dd + j]     + srp[j] + bias_r[j];
        float pg = uxrow[2 * Dd + j] + sgp[j] + bias_g[j];
        rr[i] = 1.f / (1.f + expf(-pr));
        gg[i] = 1.f / (1.f + expf(-pg));
    }
    __syncthreads();

    int cur = 0;
#pragma unroll
    for (int sidx = 0; sidx < CAP; sidx++) {
        const int mask = 512 >> sidx;
        const float* v1 = g_v1 + sidx * Dd;
        const float* v2 = g_v2 + sidx * Dd;
#pragma unroll
        for (int i = 0; i < 4; i++) {
            int j = t + i * 256;
            int e = j ^ mask;
            hbuf[cur ^ 1][j] = fmaf(hbuf[cur][j], v1[j], hbuf[cur][e] * v2[e]);
        }
        cur ^= 1;
        __syncthreads();
    }

#pragma unroll
    for (int i = 0; i < 4; i++) {
        int j = t + i * 256;
        float h   = hbuf[cur][j];
        float pre = fmaf(rr[i], h, uxrow[j]);   // r*h + U_cx
        float ac  = fabsf(pre) + 0.001f + bias_c[j];
        ac = fmaxf(ac, 0.f);
        float c = (pre > 0.f) ? ac : ((pre < 0.f) ? -ac : 0.f);
        out[(size_t)b * Dd + j] = fmaf(gg[i], st[i] - c, c);  // g*s + (1-g)*c
    }
}

// ---------------------------------------------------------------------------
extern "C" void kernel_launch(void* const* d_in, const int* in_sizes, int n_in,
                              void* d_out, int out_size) {
    const float* x      = (const float*)d_in[0];
    const float* state  = (const float*)d_in[1];
    const float* theta  = (const float*)d_in[2];
    const float* U      = (const float*)d_in[3];
    const float* W_r    = (const float*)d_in[4];
    const float* W_g    = (const float*)d_in[5];
    const float* bias_r = (const float*)d_in[6];
    const float* bias_g = (const float*)d_in[7];
    const float* bias_c = (const float*)d_in[8];
    float* out = (float*)d_out;

    float *pUx, *pSr, *pSg;
    cudaGetSymbolAddress((void**)&pUx, g_Ux);
    cudaGetSymbolAddress((void**)&pSr, g_Sr);
    cudaGetSymbolAddress((void**)&pSg, g_Sg);

    precompute_v<<<CAP, Dd>>>(theta);

    dim3 gUx(3 * Dd / 128, Bsz / 128);   // (24, 64)
    sgemm128<<<gUx, 256>>>(x, U, pUx, 3 * Dd, Kk);

    dim3 gW(Dd / 128, Bsz / 128);        // (8, 64)
    sgemm128<<<gW, 256>>>(state, W_r, pSr, Dd, Kk);
    sgemm128<<<gW, 256>>>(state, W_g, pSg, Dd, Kk);

    fuse_kernel<<<Bsz, 256>>>(state, bias_r, bias_g, bias_c, out);
}

// round 3
// speedup vs baseline: 2.7988x; 2.7988x over previous
#include <cuda_runtime.h>
#include <math.h>
#include <stdint.h>

#define Bsz 8192
#define Dd  1024
#define KTOT 1024
#define CAP 10
#define NTOT 5120            // 3*D (Ux) + D (Sr) + D (Sg)

// ---- device-global scratch (allocation-free rule) ----
__device__ float g_C[(size_t)Bsz * NTOT];    // [B, 5120]: Ucx|Urx|Ugx|Sr|Sg
__device__ float g_WT[(size_t)NTOT * KTOT];  // transposed weights, tf32-rounded
__device__ float g_Ax[(size_t)Bsz * KTOT];   // x, tf32-rounded
__device__ float g_As[(size_t)Bsz * KTOT];   // state, tf32-rounded
__device__ float g_v1[CAP * Dd];
__device__ float g_v2[CAP * Dd];

__device__ __forceinline__ float tf32r(float x) {
    asm("cvt.rna.tf32.f32 %0, %0;" : "+f"(x));
    return x;
}

// ---------------------------------------------------------------------------
// Pre-round activations to tf32 (rna, unbiased)
// ---------------------------------------------------------------------------
__global__ void __launch_bounds__(256) round_acts(const float* __restrict__ x,
                                                  const float* __restrict__ state) {
    size_t i = (size_t)blockIdx.x * 1024 + threadIdx.x * 4;
    float4 a = *(const float4*)(x + i);
    a.x = tf32r(a.x); a.y = tf32r(a.y); a.z = tf32r(a.z); a.w = tf32r(a.w);
    *(float4*)(g_Ax + i) = a;
    float4 s = *(const float4*)(state + i);
    s.x = tf32r(s.x); s.y = tf32r(s.y); s.z = tf32r(s.z); s.w = tf32r(s.w);
    *(float4*)(g_As + i) = s;
}

// ---------------------------------------------------------------------------
// Weight transpose + tf32 rounding: g_WT[n][k] = src[k][n]
// ---------------------------------------------------------------------------
__global__ void __launch_bounds__(256) transpose_weights(const float* __restrict__ U,
                                                         const float* __restrict__ Wr,
                                                         const float* __restrict__ Wg) {
    __shared__ float tile[32][33];
    const int kt = blockIdx.x * 32;
    const int nt = blockIdx.y * 32;
    const int tx = threadIdx.x & 31;
    const int ty = threadIdx.x >> 5;   // 0..7
#pragma unroll
    for (int i = 0; i < 4; i++) {
        int k = kt + ty + i * 8;
        int n = nt + tx;
        float v = (n < 3072) ? U[(size_t)k * 3072 + n]
                : (n < 4096) ? Wr[(size_t)k * 1024 + (n - 3072)]
                             : Wg[(size_t)k * 1024 + (n - 4096)];
        tile[ty + i * 8][tx] = tf32r(v);
    }
    __syncthreads();
#pragma unroll
    for (int i = 0; i < 4; i++)
        g_WT[(size_t)(nt + ty + i * 8) * KTOT + kt + tx] = tile[tx][ty + i * 8];
}

// ---------------------------------------------------------------------------
// tf32 mma.sync GEMM:  g_C[m, n] = sum_k A[m,k] * g_WT[n,k]
// CTA tile 128x128, BK=16, 8 warps (2x4), warp tile 64x32 (4x4 m16n8k8 tiles).
// cp.async double-buffered smem, stride-20 padded rows (bank-conflict-free).
// ---------------------------------------------------------------------------
#define BK 16
#define LDS_STRIDE 20                          // floats per smem row
#define STAGE_FLTS (128 * LDS_STRIDE)          // 2560 floats per operand stage

__device__ __forceinline__ void cp16(uint32_t dst, const void* src) {
    asm volatile("cp.async.cg.shared.global [%0], [%1], 16;" :: "r"(dst), "l"(src));
}
__device__ __forceinline__ uint32_t smem_u32(const void* p) {
    uint32_t a;
    asm("{ .reg .u64 t; cvta.to.shared.u64 t, %1; cvt.u32.u64 %0, t; }" : "=r"(a) : "l"(p));
    return a;
}

__global__ void __launch_bounds__(256, 2) gemm_tf32(void) {
    __shared__ float sA[2][STAGE_FLTS];
    __shared__ float sB[2][STAGE_FLTS];

    const int tid = threadIdx.x;
    const int wid = tid >> 5;
    const int lane = tid & 31;
    const int gid = lane >> 2;     // 0..7
    const int tig = lane & 3;      // 0..3
    const int wm = (wid & 1) * 64; // warp M offset
    const int wn = (wid >> 1) * 32;// warp N offset

    const int colB = blockIdx.x * 128;
    const int rowA = blockIdx.y * 128;
    const float* Ag = ((colB < 3072) ? g_Ax : g_As) + (size_t)rowA * KTOT;
    const float* Bg = g_WT + (size_t)colB * KTOT;

    // global->smem mapping: idx = tid*2 + j ; r = idx>>2 (0..127), c = idx&3
    const int r0 = (tid * 2) >> 2;
    const int c0 = (tid * 2) & 3;
    const int r1 = (tid * 2 + 1) >> 2;
    const int c1 = (tid * 2 + 1) & 3;
    const uint32_t sA_u[2] = {smem_u32(&sA[0][0]), smem_u32(&sA[1][0])};
    const uint32_t sB_u[2] = {smem_u32(&sB[0][0]), smem_u32(&sB[1][0])};

    float acc[4][4][4];
#pragma unroll
    for (int i = 0; i < 4; i++)
#pragma unroll
        for (int j = 0; j < 4; j++)
#pragma unroll
            for (int q = 0; q < 4; q++) acc[i][j][q] = 0.f;

    auto load_stage = [&](int chunk, int s) {
        const size_t k0 = (size_t)chunk * BK;
        cp16(sA_u[s] + (r0 * LDS_STRIDE + c0 * 4) * 4, Ag + (size_t)r0 * KTOT + k0 + c0 * 4);
        cp16(sA_u[s] + (r1 * LDS_STRIDE + c1 * 4) * 4, Ag + (size_t)r1 * KTOT + k0 + c1 * 4);
        cp16(sB_u[s] + (r0 * LDS_STRIDE + c0 * 4) * 4, Bg + (size_t)r0 * KTOT + k0 + c0 * 4);
        cp16(sB_u[s] + (r1 * LDS_STRIDE + c1 * 4) * 4, Bg + (size_t)r1 * KTOT + k0 + c1 * 4);
        asm volatile("cp.async.commit_group;");
    };

    load_stage(0, 0);
    asm volatile("cp.async.wait_group 0;");
    __syncthreads();

    const int NCH = KTOT / BK;   // 64
    for (int ch = 0; ch < NCH; ch++) {
        const int s = ch & 1;
        if (ch + 1 < NCH) load_stage(ch + 1, s ^ 1);

        const float* cA = sA[s];
        const float* cB = sB[s];
#pragma unroll
        for (int ks = 0; ks < 2; ks++) {
            const int kof = ks * 8 + tig;
            uint32_t a[4][4], b[4][2];
#pragma unroll
            for (int mt = 0; mt < 4; mt++) {
                const float* ap = cA + (wm + mt * 16 + gid) * LDS_STRIDE + kof;
                a[mt][0] = __float_as_uint(ap[0]);
                a[mt][1] = __float_as_uint(ap[8 * LDS_STRIDE]);
                a[mt][2] = __float_as_uint(ap[4]);
                a[mt][3] = __float_as_uint(ap[8 * LDS_STRIDE + 4]);
            }
#pragma unroll
            for (int nt = 0; nt < 4; nt++) {
                const float* bp = cB + (wn + nt * 8 + gid) * LDS_STRIDE + kof;
                b[nt][0] = __float_as_uint(bp[0]);
                b[nt][1] = __float_as_uint(bp[4]);
            }
#pragma unroll
            for (int mt = 0; mt < 4; mt++)
#pragma unroll
                for (int nt = 0; nt < 4; nt++) {
                    float* c = acc[mt][nt];
                    asm volatile(
                        "mma.sync.aligned.m16n8k8.row.col.f32.tf32.tf32.f32 "
                        "{%0,%1,%2,%3}, {%4,%5,%6,%7}, {%8,%9}, {%0,%1,%2,%3};"
                        : "+f"(c[0]), "+f"(c[1]), "+f"(c[2]), "+f"(c[3])
                        : "r"(a[mt][0]), "r"(a[mt][1]), "r"(a[mt][2]), "r"(a[mt][3]),
                          "r"(b[nt][0]), "r"(b[nt][1]));
                }
        }
        if (ch + 1 < NCH) {
            asm volatile("cp.async.wait_group 0;");
            __syncthreads();
        }
    }

    // epilogue
#pragma unroll
    for (int mt = 0; mt < 4; mt++) {
        const int m = rowA + wm + mt * 16 + gid;
        float* crow0 = g_C + (size_t)m * NTOT + colB + wn;
        float* crow1 = crow0 + 8 * NTOT;
#pragma unroll
        for (int nt = 0; nt < 4; nt++) {
            const int n = nt * 8 + tig * 2;
            float2 lo = {acc[mt][nt][0], acc[mt][nt][1]};
            float2 hi = {acc[mt][nt][2], acc[mt][nt][3]};
            *(float2*)(crow0 + n) = lo;
            *(float2*)(crow1 + n) = hi;
        }
    }
}

// ---------------------------------------------------------------------------
// Butterfly coefficient precompute
// ---------------------------------------------------------------------------
__global__ void precompute_v(const float* __restrict__ theta) {
    int i = blockIdx.x;
    int m = threadIdx.x;
    int bl = 10 - i;
    int j = m >> bl;
    int q = m & ((1 << bl) - 1);
    int src = (q << i) + j;
    float th = theta[i * 512 + (src & 511)];
    float c = cosf(th), s = sinf(th);
    if (src >= 512) s = -s;
    g_v1[i * Dd + m] = c;
    g_v2[i * Dd + m] = s;
}

// ---------------------------------------------------------------------------
// Fused gates + butterfly + modReLU + blend
// ---------------------------------------------------------------------------
__global__ void __launch_bounds__(256) fuse_kernel(const float* __restrict__ state,
                                                   const float* __restrict__ bias_r,
                                                   const float* __restrict__ bias_g,
                                                   const float* __restrict__ bias_c,
                                                   float* __restrict__ out) {
    __shared__ float hbuf[2][Dd];
    const int b = blockIdx.x;
    const int t = threadIdx.x;
    const float* srow = state + (size_t)b * Dd;
    const float* crow = g_C + (size_t)b * NTOT;

    float st[4], rr[4], gg[4];
#pragma unroll
    for (int i = 0; i < 4; i++) {
        int j = t + i * 256;
        float s = srow[j];
        st[i] = s;
        hbuf[0][j] = s;
        float pr = crow[1024 + j] + crow[3072 + j] + bias_r[j];
        float pg = crow[2048 + j] + crow[4096 + j] + bias_g[j];
        rr[i] = 1.f / (1.f + expf(-pr));
        gg[i] = 1.f / (1.f + expf(-pg));
    }
    __syncthreads();

    int cur = 0;
#pragma unroll
    for (int sidx = 0; sidx < CAP; sidx++) {
        const int mask = 512 >> sidx;
        const float* v1 = g_v1 + sidx * Dd;
        const float* v2 = g_v2 + sidx * Dd;
#pragma unroll
        for (int i = 0; i < 4; i++) {
            int j = t + i * 256;
            int e = j ^ mask;
            hbuf[cur ^ 1][j] = fmaf(hbuf[cur][j], v1[j], hbuf[cur][e] * v2[e]);
        }
        cur ^= 1;
        __syncthreads();
    }

#pragma unroll
    for (int i = 0; i < 4; i++) {
        int j = t + i * 256;
        float h = hbuf[cur][j];
        float pre = fmaf(rr[i], h, crow[j]);
        float ac = fabsf(pre) + 0.001f + bias_c[j];
        ac = fmaxf(ac, 0.f);
        float c = (pre > 0.f) ? ac : ((pre < 0.f) ? -ac : 0.f);
        out[(size_t)b * Dd + j] = fmaf(gg[i], st[i] - c, c);
    }
}

// ---------------------------------------------------------------------------
extern "C" void kernel_launch(void* const* d_in, const int* in_sizes, int n_in,
                              void* d_out, int out_size) {
    const float* x      = (const float*)d_in[0];
    const float* state  = (const float*)d_in[1];
    const float* theta  = (const float*)d_in[2];
    const float* U      = (const float*)d_in[3];
    const float* W_r    = (const float*)d_in[4];
    const float* W_g    = (const float*)d_in[5];
    const float* bias_r = (const float*)d_in[6];
    const float* bias_g = (const float*)d_in[7];
    const float* bias_c = (const float*)d_in[8];
    float* out = (float*)d_out;

    precompute_v<<<CAP, Dd>>>(theta);
    round_acts<<<(Bsz * KTOT) / 1024, 256>>>(x, state);

    dim3 gT(KTOT / 32, NTOT / 32);
    transpose_weights<<<gT, 256>>>(U, W_r, W_g);

    dim3 gG(NTOT / 128, Bsz / 128);   // (40, 64)
    gemm_tf32<<<gG, 256>>>();

    fuse_kernel<<<Bsz, 256>>>(state, bias_r, bias_g, bias_c, out);
}

// round 4
// speedup vs baseline: 3.7713x; 1.3475x over previous
#include <cuda_runtime.h>
#include <math.h>
#include <stdint.h>

#define Bsz 8192
#define Dd  1024
#define KTOT 1024
#define CAP 10
#define NTOT 5120            // 3*D (Ux) + D (Sr) + D (Sg)

// ---- device-global scratch (allocation-free rule) ----
__device__ float g_C[(size_t)Bsz * NTOT];    // [B, 5120]: Ucx|Urx|Ugx|Sr|Sg
__device__ float g_WT[(size_t)NTOT * KTOT];  // transposed weights, tf32-rounded
__device__ float g_Ax[(size_t)Bsz * KTOT];   // x, tf32-rounded
__device__ float g_As[(size_t)Bsz * KTOT];   // state, tf32-rounded
__device__ float g_v1[CAP * Dd];
__device__ float g_v2[CAP * Dd];

__device__ __forceinline__ float tf32r(float x) {
    asm("cvt.rna.tf32.f32 %0, %0;" : "+f"(x));
    return x;
}
__device__ __forceinline__ uint32_t smem_u32(const void* p) {
    uint32_t a;
    asm("{ .reg .u64 t; cvta.to.shared.u64 t, %1; cvt.u32.u64 %0, t; }" : "=r"(a) : "l"(p));
    return a;
}
__device__ __forceinline__ void cp16(uint32_t dst, const void* src) {
    asm volatile("cp.async.cg.shared.global [%0], [%1], 16;" :: "r"(dst), "l"(src));
}

// ---------------------------------------------------------------------------
// Pre-round activations to tf32 (rna, unbiased)
// ---------------------------------------------------------------------------
__global__ void __launch_bounds__(256) round_acts(const float* __restrict__ x,
                                                  const float* __restrict__ state) {
    size_t i = (size_t)blockIdx.x * 1024 + threadIdx.x * 4;
    float4 a = *(const float4*)(x + i);
    a.x = tf32r(a.x); a.y = tf32r(a.y); a.z = tf32r(a.z); a.w = tf32r(a.w);
    *(float4*)(g_Ax + i) = a;
    float4 s = *(const float4*)(state + i);
    s.x = tf32r(s.x); s.y = tf32r(s.y); s.z = tf32r(s.z); s.w = tf32r(s.w);
    *(float4*)(g_As + i) = s;
}

// ---------------------------------------------------------------------------
// Weight transpose + tf32 rounding: g_WT[n][k] = src[k][n]
// ---------------------------------------------------------------------------
__global__ void __launch_bounds__(256) transpose_weights(const float* __restrict__ U,
                                                         const float* __restrict__ Wr,
                                                         const float* __restrict__ Wg) {
    __shared__ float tile[32][33];
    const int kt = blockIdx.x * 32;
    const int nt = blockIdx.y * 32;
    const int tx = threadIdx.x & 31;
    const int ty = threadIdx.x >> 5;   // 0..7
#pragma unroll
    for (int i = 0; i < 4; i++) {
        int k = kt + ty + i * 8;
        int n = nt + tx;
        float v = (n < 3072) ? U[(size_t)k * 3072 + n]
                : (n < 4096) ? Wr[(size_t)k * 1024 + (n - 3072)]
                             : Wg[(size_t)k * 1024 + (n - 4096)];
        tile[ty + i * 8][tx] = tf32r(v);
    }
    __syncthreads();
#pragma unroll
    for (int i = 0; i < 4; i++)
        g_WT[(size_t)(nt + ty + i * 8) * KTOT + kt + tx] = tile[tx][ty + i * 8];
}

// ---------------------------------------------------------------------------
// tf32 mma.sync GEMM:  g_C[m, n] = sum_k A[m,k] * g_WT[n,k]
// CTA 128x128, BK=32, 3-stage cp.async pipeline, 8 warps (2x4), warp 64x32.
// Padded smem rows (stride 36 floats): conflict-free fragment loads.
// ---------------------------------------------------------------------------
#define BK 32
#define NCH (KTOT / BK)        // 32
#define LDSS 36                // floats per smem row
#define STG_FLTS (128 * LDSS)  // 4608 floats per operand stage
#define GEMM_SMEM (3 * 2 * STG_FLTS * 4)   // 110592 bytes

__global__ void __launch_bounds__(256, 2) gemm_tf32(void) {
    extern __shared__ float sm[];
    const uint32_t sbase = smem_u32(sm);

    const int tid = threadIdx.x;
    const int wid = tid >> 5;
    const int lane = tid & 31;
    const int gid = lane >> 2;     // 0..7
    const int tig = lane & 3;      // 0..3
    const int wm = (wid & 1) * 64; // warp M offset
    const int wn = (wid >> 1) * 32;// warp N offset

    const int colB = blockIdx.x * 128;
    const int rowA = blockIdx.y * 128;
    const float* Ag = ((colB < 3072) ? g_Ax : g_As) + (size_t)rowA * KTOT;
    const float* Bg = g_WT + (size_t)colB * KTOT;

    // global->smem mapping: 1024 float4 per operand per stage, 4 per thread
    int lr[4], lc[4];
#pragma unroll
    for (int q = 0; q < 4; q++) {
        int idx = tid + q * 256;
        lr[q] = idx >> 3;          // 0..127
        lc[q] = (idx & 7) * 4;     // 0..28
    }

    float acc[4][4][4];
#pragma unroll
    for (int i = 0; i < 4; i++)
#pragma unroll
        for (int j = 0; j < 4; j++)
#pragma unroll
            for (int q = 0; q < 4; q++) acc[i][j][q] = 0.f;

    auto load_stage = [&](int chunk, int s) {
        const size_t k0 = (size_t)chunk * BK;
        const uint32_t base = sbase + (uint32_t)s * (2 * STG_FLTS * 4);
#pragma unroll
        for (int q = 0; q < 4; q++)
            cp16(base + (lr[q] * LDSS + lc[q]) * 4, Ag + (size_t)lr[q] * KTOT + k0 + lc[q]);
#pragma unroll
        for (int q = 0; q < 4; q++)
            cp16(base + STG_FLTS * 4 + (lr[q] * LDSS + lc[q]) * 4,
                 Bg + (size_t)lr[q] * KTOT + k0 + lc[q]);
        asm volatile("cp.async.commit_group;");
    };

    load_stage(0, 0);
    load_stage(1, 1);
    asm volatile("cp.async.wait_group 1;");   // stage 0 ready
    __syncthreads();

    for (int ch = 0; ch < NCH; ch++) {
        const int s = ch % 3;
        if (ch + 2 < NCH) load_stage(ch + 2, (ch + 2) % 3);

        const float* cA = sm + s * (2 * STG_FLTS);
        const float* cB = cA + STG_FLTS;
#pragma unroll
        for (int ks = 0; ks < 4; ks++) {
            const int kof = ks * 8 + tig;
            uint32_t a[4][4], b[4][2];
#pragma unroll
            for (int mt = 0; mt < 4; mt++) {
                const float* ap = cA + (wm + mt * 16 + gid) * LDSS + kof;
                a[mt][0] = __float_as_uint(ap[0]);
                a[mt][1] = __float_as_uint(ap[8 * LDSS]);
                a[mt][2] = __float_as_uint(ap[4]);
                a[mt][3] = __float_as_uint(ap[8 * LDSS + 4]);
            }
#pragma unroll
            for (int nt = 0; nt < 4; nt++) {
                const float* bp = cB + (wn + nt * 8 + gid) * LDSS + kof;
                b[nt][0] = __float_as_uint(bp[0]);
                b[nt][1] = __float_as_uint(bp[4]);
            }
#pragma unroll
            for (int mt = 0; mt < 4; mt++)
#pragma unroll
                for (int nt = 0; nt < 4; nt++) {
                    float* c = acc[mt][nt];
                    asm volatile(
                        "mma.sync.aligned.m16n8k8.row.col.f32.tf32.tf32.f32 "
                        "{%0,%1,%2,%3}, {%4,%5,%6,%7}, {%8,%9}, {%0,%1,%2,%3};"
                        : "+f"(c[0]), "+f"(c[1]), "+f"(c[2]), "+f"(c[3])
                        : "r"(a[mt][0]), "r"(a[mt][1]), "r"(a[mt][2]), "r"(a[mt][3]),
                          "r"(b[nt][0]), "r"(b[nt][1]));
                }
        }
        if (ch + 1 < NCH) {
            if (ch + 2 < NCH) asm volatile("cp.async.wait_group 1;");
            else              asm volatile("cp.async.wait_group 0;");
            __syncthreads();
        }
    }

    // epilogue
#pragma unroll
    for (int mt = 0; mt < 4; mt++) {
        const int m = rowA + wm + mt * 16 + gid;
        float* crow0 = g_C + (size_t)m * NTOT + colB + wn;
        float* crow1 = crow0 + 8 * NTOT;
#pragma unroll
        for (int nt = 0; nt < 4; nt++) {
            const int n = nt * 8 + tig * 2;
            float2 lo = {acc[mt][nt][0], acc[mt][nt][1]};
            float2 hi = {acc[mt][nt][2], acc[mt][nt][3]};
            *(float2*)(crow0 + n) = lo;
            *(float2*)(crow1 + n) = hi;
        }
    }
}

// ---------------------------------------------------------------------------
// Butterfly coefficient precompute
// ---------------------------------------------------------------------------
__global__ void precompute_v(const float* __restrict__ theta) {
    int i = blockIdx.x;
    int m = threadIdx.x;
    int bl = 10 - i;
    int j = m >> bl;
    int q = m & ((1 << bl) - 1);
    int src = (q << i) + j;
    float th = theta[i * 512 + (src & 511)];
    float c = cosf(th), s = sinf(th);
    if (src >= 512) s = -s;
    g_v1[i * Dd + m] = c;
    g_v2[i * Dd + m] = s;
}

// ---------------------------------------------------------------------------
// Fused gates + butterfly + modReLU + blend.
// Layout: thread t owns j = 4t..4t+3.
//   masks 512,256,128 : smem exchange (partner thread t ^ mask/4), 3 syncs
//   masks 64..4       : __shfl_xor by mask/4 (1..16, intra-warp)
//   masks 2,1         : in-register
// ---------------------------------------------------------------------------
__global__ void __launch_bounds__(256) fuse_kernel(const float* __restrict__ state,
                                                   const float* __restrict__ bias_r,
                                                   const float* __restrict__ bias_g,
                                                   const float* __restrict__ bias_c,
                                                   float* __restrict__ out) {
    __shared__ float buf[2][Dd];
    const int b = blockIdx.x;
    const int t = threadIdx.x;
    const int j0 = t * 4;
    const float* crow = g_C + (size_t)b * NTOT;

    float4 s4  = *(const float4*)(state + (size_t)b * Dd + j0);
    float4 ucx = *(const float4*)(crow + j0);
    float4 urx = *(const float4*)(crow + 1024 + j0);
    float4 ugx = *(const float4*)(crow + 2048 + j0);
    float4 sr4 = *(const float4*)(crow + 3072 + j0);
    float4 sg4 = *(const float4*)(crow + 4096 + j0);
    float4 br4 = *(const float4*)(bias_r + j0);
    float4 bg4 = *(const float4*)(bias_g + j0);
    float4 bc4 = *(const float4*)(bias_c + j0);

    float st[4] = {s4.x, s4.y, s4.z, s4.w};
    float h[4]  = {s4.x, s4.y, s4.z, s4.w};
    float rr[4], gg[4];
    {
        float pr[4] = {urx.x + sr4.x + br4.x, urx.y + sr4.y + br4.y,
                       urx.z + sr4.z + br4.z, urx.w + sr4.w + br4.w};
        float pg[4] = {ugx.x + sg4.x + bg4.x, ugx.y + sg4.y + bg4.y,
                       ugx.z + sg4.z + bg4.z, ugx.w + sg4.w + bg4.w};
#pragma unroll
        for (int i = 0; i < 4; i++) {
            rr[i] = 1.f / (1.f + expf(-pr[i]));
            gg[i] = 1.f / (1.f + expf(-pg[i]));
        }
    }

    // --- stages 0..2: cross-warp via smem ---
#pragma unroll
    for (int sidx = 0; sidx < 3; sidx++) {
        const int mask = 512 >> sidx;
        const int tx = t ^ (mask >> 2);
        float4 v1 = *(const float4*)(g_v1 + sidx * Dd + j0);
        float4 v2 = *(const float4*)(g_v2 + sidx * Dd + j0);
        float4 p = {h[0] * v2.x, h[1] * v2.y, h[2] * v2.z, h[3] * v2.w};
        *(float4*)&buf[sidx & 1][j0] = p;
        __syncthreads();
        float4 q = *(const float4*)&buf[sidx & 1][tx * 4];
        h[0] = fmaf(h[0], v1.x, q.x);
        h[1] = fmaf(h[1], v1.y, q.y);
        h[2] = fmaf(h[2], v1.z, q.z);
        h[3] = fmaf(h[3], v1.w, q.w);
    }

    // --- stages 3..7: intra-warp shfl ---
#pragma unroll
    for (int sidx = 3; sidx < 8; sidx++) {
        const int mask = 512 >> sidx;
        const int lx = mask >> 2;   // 16,8,4,2,1
        float4 v1 = *(const float4*)(g_v1 + sidx * Dd + j0);
        float4 v2 = *(const float4*)(g_v2 + sidx * Dd + j0);
        float p[4] = {h[0] * v2.x, h[1] * v2.y, h[2] * v2.z, h[3] * v2.w};
        float q[4];
#pragma unroll
        for (int i = 0; i < 4; i++) q[i] = __shfl_xor_sync(0xffffffffu, p[i], lx);
        h[0] = fmaf(h[0], v1.x, q[0]);
        h[1] = fmaf(h[1], v1.y, q[1]);
        h[2] = fmaf(h[2], v1.z, q[2]);
        h[3] = fmaf(h[3], v1.w, q[3]);
    }

    // --- stage 8 (mask 2) and stage 9 (mask 1): in-register ---
    {
        float4 v1 = *(const float4*)(g_v1 + 8 * Dd + j0);
        float4 v2 = *(const float4*)(g_v2 + 8 * Dd + j0);
        float v1a[4] = {v1.x, v1.y, v1.z, v1.w};
        float v2a[4] = {v2.x, v2.y, v2.z, v2.w};
        float hn[4];
#pragma unroll
        for (int i = 0; i < 4; i++) hn[i] = fmaf(h[i], v1a[i], h[i ^ 2] * v2a[i ^ 2]);
#pragma unroll
        for (int i = 0; i < 4; i++) h[i] = hn[i];
    }
    {
        float4 v1 = *(const float4*)(g_v1 + 9 * Dd + j0);
        float4 v2 = *(const float4*)(g_v2 + 9 * Dd + j0);
        float v1a[4] = {v1.x, v1.y, v1.z, v1.w};
        float v2a[4] = {v2.x, v2.y, v2.z, v2.w};
        float hn[4];
#pragma unroll
        for (int i = 0; i < 4; i++) hn[i] = fmaf(h[i], v1a[i], h[i ^ 1] * v2a[i ^ 1]);
#pragma unroll
        for (int i = 0; i < 4; i++) h[i] = hn[i];
    }

    // --- modReLU + blend ---
    float ux[4] = {ucx.x, ucx.y, ucx.z, ucx.w};
    float bc[4] = {bc4.x, bc4.y, bc4.z, bc4.w};
    float4 o;
    float* op = &o.x;
#pragma unroll
    for (int i = 0; i < 4; i++) {
        float pre = fmaf(rr[i], h[i], ux[i]);
        float ac = fabsf(pre) + 0.001f + bc[i];
        ac = fmaxf(ac, 0.f);
        float c = (pre > 0.f) ? ac : ((pre < 0.f) ? -ac : 0.f);
        op[i] = fmaf(gg[i], st[i] - c, c);
    }
    *(float4*)(out + (size_t)b * Dd + j0) = o;
}

// ---------------------------------------------------------------------------
extern "C" void kernel_launch(void* const* d_in, const int* in_sizes, int n_in,
                              void* d_out, int out_size) {
    const float* x      = (const float*)d_in[0];
    const float* state  = (const float*)d_in[1];
    const float* theta  = (const float*)d_in[2];
    const float* U      = (const float*)d_in[3];
    const float* W_r    = (const float*)d_in[4];
    const float* W_g    = (const float*)d_in[5];
    const float* bias_r = (const float*)d_in[6];
    const float* bias_g = (const float*)d_in[7];
    const float* bias_c = (const float*)d_in[8];
    float* out = (float*)d_out;

    cudaFuncSetAttribute(gemm_tf32, cudaFuncAttributeMaxDynamicSharedMemorySize, GEMM_SMEM);

    precompute_v<<<CAP, Dd>>>(theta);
    round_acts<<<(Bsz * KTOT) / 1024, 256>>>(x, state);

    dim3 gT(KTOT / 32, NTOT / 32);
    transpose_weights<<<gT, 256>>>(U, W_r, W_g);

    dim3 gG(NTOT / 128, Bsz / 128);   // (40, 64)
    gemm_tf32<<<gG, 256, GEMM_SMEM>>>();

    fuse_kernel<<<Bsz, 256>>>(state, bias_r, bias_g, bias_c, out);
}

// round 5
// speedup vs baseline: 4.1568x; 1.1022x over previous
#include <cuda_runtime.h>
#include <math.h>
#include <stdint.h>

#define Bsz 8192
#define Dd  1024
#define KTOT 1024
#define CAP 10
#define NTOT 5120            // 3*D (Ux) + D (Sr) + D (Sg)

// ---- device-global scratch (allocation-free rule) ----
__device__ float g_C[(size_t)Bsz * NTOT];    // [B, 5120]: Ucx|Urx|Ugx|Sr|Sg
__device__ float g_WT[(size_t)NTOT * KTOT];  // transposed weights, tf32-rounded
__device__ float g_Ax[(size_t)Bsz * KTOT];   // x, tf32-rounded
__device__ float g_As[(size_t)Bsz * KTOT];   // state, tf32-rounded
__device__ float g_v1[CAP * Dd];
__device__ float g_v2[CAP * Dd];

__device__ __forceinline__ float tf32r(float x) {
    asm("cvt.rna.tf32.f32 %0, %0;" : "+f"(x));
    return x;
}
__device__ __forceinline__ uint32_t smem_u32(const void* p) {
    uint32_t a;
    asm("{ .reg .u64 t; cvta.to.shared.u64 t, %1; cvt.u32.u64 %0, t; }" : "=r"(a) : "l"(p));
    return a;
}
__device__ __forceinline__ void cp16(uint32_t dst, const void* src) {
    asm volatile("cp.async.cg.shared.global [%0], [%1], 16;" :: "r"(dst), "l"(src));
}
#define LDSM_X4(r0, r1, r2, r3, addr) \
    asm volatile("ldmatrix.sync.aligned.m8n8.x4.shared.b16 {%0,%1,%2,%3}, [%4];" \
                 : "=r"(r0), "=r"(r1), "=r"(r2), "=r"(r3) : "r"(addr))

// ---------------------------------------------------------------------------
// Pre-round activations to tf32 (rna, unbiased)
// ---------------------------------------------------------------------------
__global__ void __launch_bounds__(256) round_acts(const float* __restrict__ x,
                                                  const float* __restrict__ state) {
    size_t i = (size_t)blockIdx.x * 1024 + threadIdx.x * 4;
    float4 a = *(const float4*)(x + i);
    a.x = tf32r(a.x); a.y = tf32r(a.y); a.z = tf32r(a.z); a.w = tf32r(a.w);
    *(float4*)(g_Ax + i) = a;
    float4 s = *(const float4*)(state + i);
    s.x = tf32r(s.x); s.y = tf32r(s.y); s.z = tf32r(s.z); s.w = tf32r(s.w);
    *(float4*)(g_As + i) = s;
}

// ---------------------------------------------------------------------------
// Weight transpose + tf32 rounding: g_WT[n][k] = src[k][n]
// ---------------------------------------------------------------------------
__global__ void __launch_bounds__(256) transpose_weights(const float* __restrict__ U,
                                                         const float* __restrict__ Wr,
                                                         const float* __restrict__ Wg) {
    __shared__ float tile[32][33];
    const int kt = blockIdx.x * 32;
    const int nt = blockIdx.y * 32;
    const int tx = threadIdx.x & 31;
    const int ty = threadIdx.x >> 5;   // 0..7
#pragma unroll
    for (int i = 0; i < 4; i++) {
        int k = kt + ty + i * 8;
        int n = nt + tx;
        float v = (n < 3072) ? U[(size_t)k * 3072 + n]
                : (n < 4096) ? Wr[(size_t)k * 1024 + (n - 3072)]
                             : Wg[(size_t)k * 1024 + (n - 4096)];
        tile[ty + i * 8][tx] = tf32r(v);
    }
    __syncthreads();
#pragma unroll
    for (int i = 0; i < 4; i++)
        g_WT[(size_t)(nt + ty + i * 8) * KTOT + kt + tx] = tile[tx][ty + i * 8];
}

// ---------------------------------------------------------------------------
// tf32 mma.sync GEMM:  g_C[m, n] = sum_k A[m,k] * g_WT[n,k]
// CTA 128x128, BK=32, 3-stage cp.async pipeline, 8 warps (2x4), warp 64x32.
// Fragments via ldmatrix.x4 (1 instr per A mt-tile, 1 per B nt-pair).
// Padded smem rows (stride 36 floats = 144B): ldmatrix rows shift banks by 4
// per row -> each 8-row phase covers all 32 banks once (conflict-free).
// ---------------------------------------------------------------------------
#define BK 32
#define NCH (KTOT / BK)        // 32
#define LDSS 36                // floats per smem row
#define ROWB (LDSS * 4)        // 144 bytes per row
#define STG_FLTS (128 * LDSS)  // 4608 floats per operand stage
#define GEMM_SMEM (3 * 2 * STG_FLTS * 4)   // 110592 bytes

__global__ void __launch_bounds__(256, 2) gemm_tf32(void) {
    extern __shared__ float sm[];
    const uint32_t sbase = smem_u32(sm);

    const int tid = threadIdx.x;
    const int wid = tid >> 5;
    const int lane = tid & 31;
    const int gid = lane >> 2;     // 0..7
    const int tig = lane & 3;      // 0..3
    const int wm = (wid & 1) * 64; // warp M offset
    const int wn = (wid >> 1) * 32;// warp N offset

    const int colB = blockIdx.x * 128;
    const int rowA = blockIdx.y * 128;
    const float* Ag = ((colB < 3072) ? g_Ax : g_As) + (size_t)rowA * KTOT;
    const float* Bg = g_WT + (size_t)colB * KTOT;

    // ldmatrix lane-address offsets (within a stage, bytes):
    // A (x4 = rows 0-15 x k 0-7): row = lane&15, col-half = lane>>4
    const uint32_t aOff = (uint32_t)(wm + (lane & 15)) * ROWB + ((lane >> 4) << 4);
    // B (x4 = two n-octets x k 0-7): row = ((lane>>4)<<3)+(lane&7), half = (lane>>3)&1
    const uint32_t bOff = (uint32_t)(wn + (((lane >> 4) & 1) << 3) + (lane & 7)) * ROWB
                        + (((lane >> 3) & 1) << 4);

    // global->smem store mapping: 1024 float4 per operand per stage, 4/thread
    int lr[4], lc[4];
#pragma unroll
    for (int q = 0; q < 4; q++) {
        int idx = tid + q * 256;
        lr[q] = idx >> 3;          // 0..127
        lc[q] = (idx & 7) * 4;     // 0..28
    }

    float acc[4][4][4];
#pragma unroll
    for (int i = 0; i < 4; i++)
#pragma unroll
        for (int j = 0; j < 4; j++)
#pragma unroll
            for (int q = 0; q < 4; q++) acc[i][j][q] = 0.f;

    auto load_stage = [&](int chunk, int s) {
        const size_t k0 = (size_t)chunk * BK;
        const uint32_t base = sbase + (uint32_t)s * (2 * STG_FLTS * 4);
#pragma unroll
        for (int q = 0; q < 4; q++)
            cp16(base + (lr[q] * LDSS + lc[q]) * 4, Ag + (size_t)lr[q] * KTOT + k0 + lc[q]);
#pragma unroll
        for (int q = 0; q < 4; q++)
            cp16(base + STG_FLTS * 4 + (lr[q] * LDSS + lc[q]) * 4,
                 Bg + (size_t)lr[q] * KTOT + k0 + lc[q]);
        asm volatile("cp.async.commit_group;");
    };

    load_stage(0, 0);
    load_stage(1, 1);
    asm volatile("cp.async.wait_group 1;");   // stage 0 ready
    __syncthreads();

    for (int ch = 0; ch < NCH; ch++) {
        const int s = ch % 3;
        if (ch + 2 < NCH) load_stage(ch + 2, (ch + 2) % 3);

        const uint32_t cA_u = sbase + (uint32_t)s * (2 * STG_FLTS * 4);
        const uint32_t cB_u = cA_u + STG_FLTS * 4;
#pragma unroll
        for (int ks = 0; ks < 4; ks++) {
            uint32_t a[4][4], b[4][2];
            const uint32_t kb = (uint32_t)ks * 32;
#pragma unroll
            for (int mt = 0; mt < 4; mt++)
                LDSM_X4(a[mt][0], a[mt][1], a[mt][2], a[mt][3],
                        cA_u + aOff + (uint32_t)mt * (16 * ROWB) + kb);
#pragma unroll
            for (int np = 0; np < 2; np++)
                LDSM_X4(b[np * 2][0], b[np * 2][1], b[np * 2 + 1][0], b[np * 2 + 1][1],
                        cB_u + bOff + (uint32_t)np * (16 * ROWB) + kb);
#pragma unroll
            for (int mt = 0; mt < 4; mt++)
#pragma unroll
                for (int nt = 0; nt < 4; nt++) {
                    float* c = acc[mt][nt];
                    asm volatile(
                        "mma.sync.aligned.m16n8k8.row.col.f32.tf32.tf32.f32 "
                        "{%0,%1,%2,%3}, {%4,%5,%6,%7}, {%8,%9}, {%0,%1,%2,%3};"
                        : "+f"(c[0]), "+f"(c[1]), "+f"(c[2]), "+f"(c[3])
                        : "r"(a[mt][0]), "r"(a[mt][1]), "r"(a[mt][2]), "r"(a[mt][3]),
                          "r"(b[nt][0]), "r"(b[nt][1]));
                }
        }
        if (ch + 1 < NCH) {
            if (ch + 2 < NCH) asm volatile("cp.async.wait_group 1;");
            else              asm volatile("cp.async.wait_group 0;");
            __syncthreads();
        }
    }

    // epilogue
#pragma unroll
    for (int mt = 0; mt < 4; mt++) {
        const int m = rowA + wm + mt * 16 + gid;
        float* crow0 = g_C + (size_t)m * NTOT + colB + wn;
        float* crow1 = crow0 + 8 * NTOT;
#pragma unroll
        for (int nt = 0; nt < 4; nt++) {
            const int n = nt * 8 + tig * 2;
            float2 lo = {acc[mt][nt][0], acc[mt][nt][1]};
            float2 hi = {acc[mt][nt][2], acc[mt][nt][3]};
            *(float2*)(crow0 + n) = lo;
            *(float2*)(crow1 + n) = hi;
        }
    }
}

// ---------------------------------------------------------------------------
// Butterfly coefficient precompute
// ---------------------------------------------------------------------------
__global__ void precompute_v(const float* __restrict__ theta) {
    int i = blockIdx.x;
    int m = threadIdx.x;
    int bl = 10 - i;
    int j = m >> bl;
    int q = m & ((1 << bl) - 1);
    int src = (q << i) + j;
    float th = theta[i * 512 + (src & 511)];
    float c = cosf(th), s = sinf(th);
    if (src >= 512) s = -s;
    g_v1[i * Dd + m] = c;
    g_v2[i * Dd + m] = s;
}

// ---------------------------------------------------------------------------
// Fused gates + butterfly + modReLU + blend.
// Thread t owns j = 4t..4t+3: smem for masks 512/256/128, shfl for 64..4,
// in-register for 2/1.
// ---------------------------------------------------------------------------
__global__ void __launch_bounds__(256) fuse_kernel(const float* __restrict__ state,
                                                   const float* __restrict__ bias_r,
                                                   const float* __restrict__ bias_g,
                                                   const float* __restrict__ bias_c,
                                                   float* __restrict__ out) {
    __shared__ float buf[2][Dd];
    const int b = blockIdx.x;
    const int t = threadIdx.x;
    const int j0 = t * 4;
    const float* crow = g_C + (size_t)b * NTOT;

    float4 s4  = *(const float4*)(state + (size_t)b * Dd + j0);
    float4 ucx = *(const float4*)(crow + j0);
    float4 urx = *(const float4*)(crow + 1024 + j0);
    float4 ugx = *(const float4*)(crow + 2048 + j0);
    float4 sr4 = *(const float4*)(crow + 3072 + j0);
    float4 sg4 = *(const float4*)(crow + 4096 + j0);
    float4 br4 = *(const float4*)(bias_r + j0);
    float4 bg4 = *(const float4*)(bias_g + j0);
    float4 bc4 = *(const float4*)(bias_c + j0);

    float st[4] = {s4.x, s4.y, s4.z, s4.w};
    float h[4]  = {s4.x, s4.y, s4.z, s4.w};
    float rr[4], gg[4];
    {
        float pr[4] = {urx.x + sr4.x + br4.x, urx.y + sr4.y + br4.y,
                       urx.z + sr4.z + br4.z, urx.w + sr4.w + br4.w};
        float pg[4] = {ugx.x + sg4.x + bg4.x, ugx.y + sg4.y + bg4.y,
                       ugx.z + sg4.z + bg4.z, ugx.w + sg4.w + bg4.w};
#pragma unroll
        for (int i = 0; i < 4; i++) {
            rr[i] = 1.f / (1.f + expf(-pr[i]));
            gg[i] = 1.f / (1.f + expf(-pg[i]));
        }
    }

#pragma unroll
    for (int sidx = 0; sidx < 3; sidx++) {
        const int mask = 512 >> sidx;
        const int tx = t ^ (mask >> 2);
        float4 v1 = *(const float4*)(g_v1 + sidx * Dd + j0);
        float4 v2 = *(const float4*)(g_v2 + sidx * Dd + j0);
        float4 p = {h[0] * v2.x, h[1] * v2.y, h[2] * v2.z, h[3] * v2.w};
        *(float4*)&buf[sidx & 1][j0] = p;
        __syncthreads();
        float4 q = *(const float4*)&buf[sidx & 1][tx * 4];
        h[0] = fmaf(h[0], v1.x, q.x);
        h[1] = fmaf(h[1], v1.y, q.y);
        h[2] = fmaf(h[2], v1.z, q.z);
        h[3] = fmaf(h[3], v1.w, q.w);
    }

#pragma unroll
    for (int sidx = 3; sidx < 8; sidx++) {
        const int mask = 512 >> sidx;
        const int lx = mask >> 2;   // 16,8,4,2,1
        float4 v1 = *(const float4*)(g_v1 + sidx * Dd + j0);
        float4 v2 = *(const float4*)(g_v2 + sidx * Dd + j0);
        float p[4] = {h[0] * v2.x, h[1] * v2.y, h[2] * v2.z, h[3] * v2.w};
        float q[4];
#pragma unroll
        for (int i = 0; i < 4; i++) q[i] = __shfl_xor_sync(0xffffffffu, p[i], lx);
        h[0] = fmaf(h[0], v1.x, q[0]);
        h[1] = fmaf(h[1], v1.y, q[1]);
        h[2] = fmaf(h[2], v1.z, q[2]);
        h[3] = fmaf(h[3], v1.w, q[3]);
    }

    {
        float4 v1 = *(const float4*)(g_v1 + 8 * Dd + j0);
        float4 v2 = *(const float4*)(g_v2 + 8 * Dd + j0);
        float v1a[4] = {v1.x, v1.y, v1.z, v1.w};
        float v2a[4] = {v2.x, v2.y, v2.z, v2.w};
        float hn[4];
#pragma unroll
        for (int i = 0; i < 4; i++) hn[i] = fmaf(h[i], v1a[i], h[i ^ 2] * v2a[i ^ 2]);
#pragma unroll
        for (int i = 0; i < 4; i++) h[i] = hn[i];
    }
    {
        float4 v1 = *(const float4*)(g_v1 + 9 * Dd + j0);
        float4 v2 = *(const float4*)(g_v2 + 9 * Dd + j0);
        float v1a[4] = {v1.x, v1.y, v1.z, v1.w};
        float v2a[4] = {v2.x, v2.y, v2.z, v2.w};
        float hn[4];
#pragma unroll
        for (int i = 0; i < 4; i++) hn[i] = fmaf(h[i], v1a[i], h[i ^ 1] * v2a[i ^ 1]);
#pragma unroll
        for (int i = 0; i < 4; i++) h[i] = hn[i];
    }

    float ux[4] = {ucx.x, ucx.y, ucx.z, ucx.w};
    float bc[4] = {bc4.x, bc4.y, bc4.z, bc4.w};
    float4 o;
    float* op = &o.x;
#pragma unroll
    for (int i = 0; i < 4; i++) {
        float pre = fmaf(rr[i], h[i], ux[i]);
        float ac = fabsf(pre) + 0.001f + bc[i];
        ac = fmaxf(ac, 0.f);
        float c = (pre > 0.f) ? ac : ((pre < 0.f) ? -ac : 0.f);
        op[i] = fmaf(gg[i], st[i] - c, c);
    }
    *(float4*)(out + (size_t)b * Dd + j0) = o;
}

// ---------------------------------------------------------------------------
extern "C" void kernel_launch(void* const* d_in, const int* in_sizes, int n_in,
                              void* d_out, int out_size) {
    const float* x      = (const float*)d_in[0];
    const float* state  = (const float*)d_in[1];
    const float* theta  = (const float*)d_in[2];
    const float* U      = (const float*)d_in[3];
    const float* W_r    = (const float*)d_in[4];
    const float* W_g    = (const float*)d_in[5];
    const float* bias_r = (const float*)d_in[6];
    const float* bias_g = (const float*)d_in[7];
    const float* bias_c = (const float*)d_in[8];
    float* out = (float*)d_out;

    cudaFuncSetAttribute(gemm_tf32, cudaFuncAttributeMaxDynamicSharedMemorySize, GEMM_SMEM);

    precompute_v<<<CAP, Dd>>>(theta);
    round_acts<<<(Bsz * KTOT) / 1024, 256>>>(x, state);

    dim3 gT(KTOT / 32, NTOT / 32);
    transpose_weights<<<gT, 256>>>(U, W_r, W_g);

    dim3 gG(NTOT / 128, Bsz / 128);   // (40, 64)
    gemm_tf32<<<gG, 256, GEMM_SMEM>>>();

    fuse_kernel<<<Bsz, 256>>>(state, bias_r, bias_g, bias_c, out);
}